// round 8
// baseline (speedup 1.0000x reference)
#include <cuda_runtime.h>
#include <cuda_bf16.h>
#include <math.h>
#include <stdint.h>

// Problem constants
#define B 2
#define C 128
#define H 128
#define W 128
#define HP 130
#define WP 130
#define NPT 9
#define CO 128
#define BHW (B * H * W)

// Scratch (device globals; allocation-free)
__device__ __align__(16) float g_xp[B * HP * WP * C];           // padded NHWC x (~17.3 MB)
__device__ __align__(16) float4 g_gates2[NPT * BHW];            // gates [n][pix] (lt,rb,lb,rt)
__device__ __align__(16) int4   g_offs2 [NPT * BHW];            // corner spatial offsets [n][pix]
__device__ __align__(16) float g_part[27 * BHW];                // offset conv outputs [ch][pix]
// bf16 hi/lo weight tiles, 18 tiles (tap n x ci-half):
//   main conv:   [co 128][k 64]
//   offset conv: [ch 32(27 pad)][k 64]
__device__ __align__(16) unsigned short g_wA_hi[18 * 8192];
__device__ __align__(16) unsigned short g_wA_lo[18 * 8192];
__device__ __align__(16) unsigned short g_wO_hi[18 * 2048];
__device__ __align__(16) unsigned short g_wO_lo[18 * 2048];

// ---------------------------------------------------------------------------
// PTX helpers (all sm_80-era: no arch-"a" gated instructions)
__device__ __forceinline__ uint32_t smem_u32(const void* p) {
    uint32_t a;
    asm("{ .reg .u64 t; cvta.to.shared.u64 t, %1; cvt.u32.u64 %0, t; }" : "=r"(a) : "l"(p));
    return a;
}
__device__ __forceinline__ void ldmx4(uint32_t* r, uint32_t a) {
    asm volatile("ldmatrix.sync.aligned.m8n8.x4.shared.b16 {%0,%1,%2,%3}, [%4];"
                 : "=r"(r[0]), "=r"(r[1]), "=r"(r[2]), "=r"(r[3]) : "r"(a));
}
__device__ __forceinline__ void ldmx2(uint32_t& r0, uint32_t& r1, uint32_t a) {
    asm volatile("ldmatrix.sync.aligned.m8n8.x2.shared.b16 {%0,%1}, [%2];"
                 : "=r"(r0), "=r"(r1) : "r"(a));
}
__device__ __forceinline__ void mma_bf16(float* c, const uint32_t* a, uint32_t b0, uint32_t b1) {
    asm volatile(
        "mma.sync.aligned.m16n8k16.row.col.f32.bf16.bf16.f32 "
        "{%0,%1,%2,%3}, {%4,%5,%6,%7}, {%8,%9}, {%0,%1,%2,%3};"
        : "+f"(c[0]), "+f"(c[1]), "+f"(c[2]), "+f"(c[3])
        : "r"(a[0]), "r"(a[1]), "r"(a[2]), "r"(a[3]), "r"(b0), "r"(b1));
}
__device__ __forceinline__ void bf16_split(float v, uint16_t& hi, uint16_t& lo) {
    __nv_bfloat16 h = __float2bfloat16_rn(v);
    __nv_bfloat16 l = __float2bfloat16_rn(v - __bfloat162float(h));
    hi = __bfloat16_as_ushort(h);
    lo = __bfloat16_as_ushort(l);
}
__device__ __forceinline__ uint32_t pack2(uint16_t a, uint16_t b) {
    return (uint32_t)a | ((uint32_t)b << 16);
}
__device__ __forceinline__ void cp16(uint32_t dst, const void* src) {
    asm volatile("cp.async.ca.shared.global [%0], [%1], 16;" :: "r"(dst), "l"(src));
}
__device__ __forceinline__ void cp_commit() {
    asm volatile("cp.async.commit_group;" ::: "memory");
}
template <int N>
__device__ __forceinline__ void cp_wait() {
    asm volatile("cp.async.wait_group %0;" :: "n"(N) : "memory");
}

// ---------------------------------------------------------------------------
// Kernel 0: zero only the pad border of g_xp (interior fully overwritten)
__global__ void zero_border_kernel() {
    int i = blockIdx.x * blockDim.x + threadIdx.x;
    if (i >= B * 516 * 32) return;
    int q = i & 31;
    int p = i >> 5;
    int b = p / 516;
    int r = p - b * 516;
    int hh, ww;
    if (r < 130)      { hh = 0;        ww = r; }
    else if (r < 260) { hh = 129;      ww = r - 130; }
    else if (r < 388) { hh = r - 259;  ww = 0; }
    else              { hh = r - 387;  ww = 129; }
    reinterpret_cast<float4*>(g_xp)[((size_t)(b * HP + hh) * WP + ww) * 32 + q] =
        make_float4(0.f, 0.f, 0.f, 0.f);
}

// ---------------------------------------------------------------------------
// Kernel 1: weight re-layouts -> bf16 hi/lo tiles (main + offset conv)
__global__ void prep_weights_kernel(const float* __restrict__ wp,
                                    const float* __restrict__ wm,
                                    const float* __restrict__ wc) {
    const int n_off = 18 * 32 * 64;          // 36864
    const int n_wa  = 18 * 128 * 64;         // 147456
    for (int e = blockIdx.x * blockDim.x + threadIdx.x; e < n_off + n_wa;
         e += gridDim.x * blockDim.x) {
        if (e < n_off) {
            int tile = e >> 11;
            int r = e & 2047;
            int ch = r >> 6;
            int c = r & 63;
            int n = tile >> 1, half = tile & 1;
            int ci = half * 64 + c;
            float v = 0.f;
            if (ch < 18)      v = wp[(ch * C + ci) * 9 + n];
            else if (ch < 27) v = wm[((ch - 18) * C + ci) * 9 + n];
            uint16_t hi, lo;
            bf16_split(v, hi, lo);
            g_wO_hi[e] = hi;
            g_wO_lo[e] = lo;
        } else {
            int t = e - n_off;
            int tile = t >> 13;
            int r = t & 8191;
            int co = r >> 6;
            int c = r & 63;
            int n = tile >> 1, half = tile & 1;
            int ci = half * 64 + c;
            float v = wc[(co * C + ci) * 9 + n];
            uint16_t hi, lo;
            bf16_split(v, hi, lo);
            g_wA_hi[t] = hi;
            g_wA_lo[t] = lo;
        }
    }
}

// ---------------------------------------------------------------------------
// Kernel 2: pad + transpose NCHW -> padded NHWC
__global__ void pad_transpose_kernel(const float* __restrict__ x) {
    __shared__ float tile[32][33];
    int w0 = blockIdx.x * 32;
    int c0 = blockIdx.y * 32;
    int bh = blockIdx.z;
    int b = bh >> 7, h = bh & 127;
    int tx = threadIdx.x, ty = threadIdx.y;
#pragma unroll
    for (int r = 0; r < 4; ++r) {
        int ci = c0 + ty + r * 8;
        tile[ty + r * 8][tx] = x[(((size_t)b * C + ci) * H + h) * W + w0 + tx];
    }
    __syncthreads();
#pragma unroll
    for (int r = 0; r < 4; ++r) {
        int w = w0 + ty + r * 8;
        g_xp[(((size_t)b * HP + h + 1) * WP + (w + 1)) * C + c0 + tx] = tile[tx][ty + r * 8];
    }
}

// ---------------------------------------------------------------------------
// Kernel 3a: offset/mask conv via HMMA, tap-shift trick + all-taps-resident W.
// Per ci-half: stage U (3 rows x 66 pix) once, cp.async ALL 9 taps' W, then
// run 9 taps x 4 k-steps of MMA with no intervening barriers (4 barriers total).
// CTA = 27(32) ch x 64 pixels, 256 thr, 1 CTA/SM (140 KB smem).
#define SC_UROW (66 * 144)              // 9504 B per xp row
#define SC_UHI 0                        // 3 rows hi: 28512
#define SC_ULO (3 * SC_UROW)            // 3 rows lo: 28512
#define SC_W   (6 * SC_UROW)            // 9 taps x (hi 4608 + lo 4608) = 82944
#define SC_TOTAL (SC_W + 9 * 9216)      // 139968 B
__global__ __launch_bounds__(256, 1) void conv_mma_kernel() {
    extern __shared__ __align__(128) char smem[];
    uint32_t sb = smem_u32(smem);
    int tid = threadIdx.x;
    int wid = tid >> 5, lane = tid & 31;

    int idx = blockIdx.x;
    int b = idx >> 8;
    int h = (idx >> 1) & 127;
    int w0 = (idx & 1) * 64;

    const float4* xb4 = reinterpret_cast<const float4*>(g_xp) + (size_t)b * HP * WP * 32;

    int wm = (wid & 1) * 16;          // ch half
    int wn = (wid >> 1) * 16;         // pixel quarter

    int asel = lane >> 3;
    int aRow = ((asel & 1) << 3) + (lane & 7);
    int aK = (asel >> 1) << 3;
    uint32_t aBase = (uint32_t)((wm + aRow) * 144 + aK * 2);
    uint32_t bPix = (uint32_t)(wn + (lane & 7));
    uint32_t bKoff = (uint32_t)((((lane >> 3) & 1) << 3) * 2);

    float acc[2][4];
#pragma unroll
    for (int nt = 0; nt < 2; ++nt)
#pragma unroll
        for (int j = 0; j < 4; ++j) acc[nt][j] = 0.f;

    for (int half = 0; half < 2; ++half) {
        __syncthreads();   // previous MMAs done; U + W buffers reusable

        // cp.async ALL 9 taps' W for this ci-half (4608 float4)
#pragma unroll
        for (int i = 0; i < 18; ++i) {
            int e = tid + i * 256;
            int tap = e >> 9;
            int r = e & 511;
            int isLo = r >> 8;
            int j = r & 255;
            uint32_t off = (uint32_t)(SC_W + tap * 9216 + isLo * 4608 + (j >> 3) * 144 + (j & 7) * 16);
            const float4* src = reinterpret_cast<const float4*>(isLo ? g_wO_lo : g_wO_hi) +
                                (tap * 2 + half) * 256 + j;
            cp16(sb + off, src);
        }
        cp_commit();

        // stage U: 3 rows x 66 pixels x 16 float4, hi/lo split
        for (int i = tid; i < 3 * 66 * 16; i += 256) {
            int row = i / (66 * 16);
            int rem = i - row * (66 * 16);
            int pix = rem >> 4;
            int q = rem & 15;
            float4 v = xb4[((size_t)(h + row) * WP + (w0 + pix)) * 32 + half * 16 + q];
            uint16_t hx, lx, hy, ly, hz, lz, hw_, lw_;
            bf16_split(v.x, hx, lx);
            bf16_split(v.y, hy, ly);
            bf16_split(v.z, hz, lz);
            bf16_split(v.w, hw_, lw_);
            uint32_t uoff = (uint32_t)(row * SC_UROW + pix * 144 + q * 8);
            *reinterpret_cast<uint2*>(smem + SC_UHI + uoff) = make_uint2(pack2(hx, hy), pack2(hz, hw_));
            *reinterpret_cast<uint2*>(smem + SC_ULO + uoff) = make_uint2(pack2(lx, ly), pack2(lz, lw_));
        }
        cp_wait<0>();
        __syncthreads();

        // MMA: 9 taps x 4 k-steps, no barriers
#pragma unroll
        for (int tap = 0; tap < 9; ++tap) {
            int dh = tap / 3, dw = tap - dh * 3;
            uint32_t wbase = (uint32_t)(SC_W + tap * 9216);
            uint32_t ubase = (uint32_t)(dh * SC_UROW) + (bPix + dw) * 144 + bKoff;
#pragma unroll
            for (int ks = 0; ks < 4; ++ks) {
                uint32_t AH[4], AL[4];
                uint32_t ao = wbase + aBase + (uint32_t)(ks * 32);
                ldmx4(AH, sb + ao);
                ldmx4(AL, sb + 4608 + ao);
#pragma unroll
                for (int nt = 0; nt < 2; ++nt) {
                    uint32_t bo = ubase + (uint32_t)(nt * 8 * 144 + ks * 32);
                    uint32_t bh0, bh1, bl0, bl1;
                    ldmx2(bh0, bh1, sb + SC_UHI + bo);
                    mma_bf16(acc[nt], AH, bh0, bh1);
                    mma_bf16(acc[nt], AL, bh0, bh1);
                    ldmx2(bl0, bl1, sb + SC_ULO + bo);
                    mma_bf16(acc[nt], AH, bl0, bl1);
                }
            }
        }
    }

    int g4 = lane >> 2, t4 = lane & 3;
    int pixbase = (b * H + h) * W + w0;
#pragma unroll
    for (int nt = 0; nt < 2; ++nt) {
        int px = wn + nt * 8 + t4 * 2;
        int ch = wm + g4;
        if (ch < 27)
            *reinterpret_cast<float2*>(&g_part[(size_t)ch * BHW + pixbase + px]) =
                make_float2(acc[nt][0], acc[nt][1]);
        if (ch + 8 < 27)
            *reinterpret_cast<float2*>(&g_part[(size_t)(ch + 8) * BHW + pixbase + px]) =
                make_float2(acc[nt][2], acc[nt][3]);
    }
}

// ---------------------------------------------------------------------------
// Kernel 3b: bias + sigmoid + bilinear gate/index precompute (tap-major layout)
__global__ __launch_bounds__(128) void off_comb_kernel(const float* __restrict__ bp,
                                                       const float* __restrict__ bm) {
    int bh = blockIdx.x;
    int b = bh >> 7, h = bh & 127;
    int w = threadIdx.x;
    int pix = bh * 128 + w;

    float acc[27];
#pragma unroll
    for (int ch = 0; ch < 18; ++ch) acc[ch] = bp[ch] + g_part[(size_t)ch * BHW + pix];
#pragma unroll
    for (int ch = 18; ch < 27; ++ch) acc[ch] = bm[ch - 18] + g_part[(size_t)ch * BHW + pix];

#pragma unroll
    for (int n = 0; n < NPT; ++n) {
        float m = 1.f / (1.f + expf(-acc[18 + n]));
        float px = acc[n]     + (float)(h + 1) + (float)(n / 3 - 1);
        float py = acc[9 + n] + (float)(w + 1) + (float)(n % 3 - 1);
        float fx = floorf(px), fy = floorf(py);
        float qltx = fminf(fmaxf(fx,       0.f), 129.f);
        float qlty = fminf(fmaxf(fy,       0.f), 129.f);
        float qrbx = fminf(fmaxf(fx + 1.f, 0.f), 129.f);
        float qrby = fminf(fmaxf(fy + 1.f, 0.f), 129.f);
        float pxc = fminf(fmaxf(px, 0.f), 129.f);
        float pyc = fminf(fmaxf(py, 0.f), 129.f);
        float ax = 1.f + (qltx - pxc);
        float bx = 1.f - (qrbx - pxc);
        float ay = 1.f + (qlty - pyc);
        float by = 1.f - (qrby - pyc);
        int ilt_x = (int)qltx, ilt_y = (int)qlty;
        int irb_x = (int)qrbx, irb_y = (int)qrby;
        g_gates2[n * BHW + pix] = make_float4(ax * ay * m, bx * by * m, ax * by * m, bx * ay * m);
        g_offs2 [n * BHW + pix] = make_int4(ilt_x * WP + ilt_y, irb_x * WP + irb_y,
                                            ilt_x * WP + irb_y, irb_x * WP + ilt_y);
    }
}

// ---------------------------------------------------------------------------
// Kernel 4: fused gather + bf16-split GEMM on warp-level mma (HMMA).
// CTA = 128 co x 64 pixels, 256 thr, 2 CTAs/SM.
// W double-buffered via cp.async prefetch (chunk k+1 staged under chunk k's gather).
#define SM_WBUF 36864                    // per-buffer: hi 18432 + lo 18432
#define SM_UHI  (2 * SM_WBUF)            // 73728
#define SM_ULO  (SM_UHI + 9216)          // 82944
#define SM_TOTAL (SM_ULO + 9216)         // 92160
__device__ __forceinline__ void stage_w_main(uint32_t sb, int buf, int chunk, int tid) {
    uint32_t wb = sb + (uint32_t)(buf * SM_WBUF);
    const float4* ah = reinterpret_cast<const float4*>(g_wA_hi) + chunk * 1024;
    const float4* al = reinterpret_cast<const float4*>(g_wA_lo) + chunk * 1024;
#pragma unroll
    for (int i = 0; i < 4; ++i) {
        int e = tid + i * 256;
        uint32_t off = (uint32_t)((e >> 3) * 144 + (e & 7) * 16);
        cp16(wb + off, ah + e);
        cp16(wb + 18432 + off, al + e);
    }
}
__global__ __launch_bounds__(256, 2) void mma_main_kernel(float* __restrict__ out) {
    extern __shared__ __align__(128) char smem[];
    uint32_t sb = smem_u32(smem);
    int tid = threadIdx.x;
    int wid = tid >> 5, lane = tid & 31;

    int idx = blockIdx.x;
    int b = idx >> 8;
    int h = (idx >> 1) & 127;
    int w0 = (idx & 1) * 64;

    int pixl = tid >> 2;
    int qt = tid & 3;
    int gpix = (b * H + h) * W + w0 + pixl;
    const float4* xb4 = reinterpret_cast<const float4*>(g_xp) + (size_t)b * HP * WP * 32;

    int wm = (wid & 1) * 64;
    int wn = (wid >> 1) * 16;

    int asel = lane >> 3;
    int aRow = ((asel & 1) << 3) + (lane & 7);
    int aK = (asel >> 1) << 3;
    uint32_t aBase = (uint32_t)((wm + aRow) * 144 + aK * 2);
    uint32_t bBase = (uint32_t)(SM_UHI + (wn + (lane & 7)) * 144 + (((lane >> 3) & 1) << 3) * 2);

    float acc[4][2][4];
#pragma unroll
    for (int mt = 0; mt < 4; ++mt)
#pragma unroll
        for (int nt = 0; nt < 2; ++nt)
#pragma unroll
            for (int j = 0; j < 4; ++j) acc[mt][nt][j] = 0.f;

    // prologue: prefetch W chunk 0
    stage_w_main(sb, 0, 0, tid);
    cp_commit();

    for (int chunk = 0; chunk < 18; ++chunk) {
        int n = chunk >> 1, half = chunk & 1;
        uint32_t wbase = (uint32_t)((chunk & 1) * SM_WBUF);
        __syncthreads();   // U free (prev MMA done); W buffer (chunk+1)&1 free

        if (chunk < 17) {
            stage_w_main(sb, (chunk + 1) & 1, chunk + 1, tid);
            cp_commit();
        }

        // gather + bf16 split into U tiles ([pix][k] = B^T layout)
        float4 g = g_gates2[n * BHW + gpix];
        int4  o = g_offs2 [n * BHW + gpix];
#pragma unroll
        for (int q = 0; q < 4; ++q) {
            int cb = half * 16 + qt * 4 + q;
            float4 v0 = xb4[(size_t)o.x * 32 + cb];
            float4 v1 = xb4[(size_t)o.y * 32 + cb];
            float4 v2 = xb4[(size_t)o.z * 32 + cb];
            float4 v3 = xb4[(size_t)o.w * 32 + cb];
            float4 v;
            v.x = fmaf(g.w, v3.x, fmaf(g.z, v2.x, fmaf(g.y, v1.x, g.x * v0.x)));
            v.y = fmaf(g.w, v3.y, fmaf(g.z, v2.y, fmaf(g.y, v1.y, g.x * v0.y)));
            v.z = fmaf(g.w, v3.z, fmaf(g.z, v2.z, fmaf(g.y, v1.z, g.x * v0.z)));
            v.w = fmaf(g.w, v3.w, fmaf(g.z, v2.w, fmaf(g.y, v1.w, g.x * v0.w)));

            uint16_t hx, lx, hy, ly, hz, lz, hw_, lw_;
            bf16_split(v.x, hx, lx);
            bf16_split(v.y, hy, ly);
            bf16_split(v.z, hz, lz);
            bf16_split(v.w, hw_, lw_);

            uint32_t uoff = (uint32_t)(pixl * 144 + (qt * 4 + q) * 8);
            *reinterpret_cast<uint2*>(smem + SM_UHI + uoff) = make_uint2(pack2(hx, hy), pack2(hz, hw_));
            *reinterpret_cast<uint2*>(smem + SM_ULO + uoff) = make_uint2(pack2(lx, ly), pack2(lz, lw_));
        }

        // wait for current chunk's W (leave the prefetch in flight)
        if (chunk < 17) cp_wait<1>();
        else            cp_wait<0>();
        __syncthreads();

        // HMMA: 4 k-steps of 16
#pragma unroll
        for (int ks = 0; ks < 4; ++ks) {
            uint32_t AH[4][4], AL[4][4];
#pragma unroll
            for (int mt = 0; mt < 4; ++mt) {
                uint32_t ao = wbase + aBase + (uint32_t)(mt * 16 * 144 + ks * 32);
                ldmx4(AH[mt], sb + ao);
                ldmx4(AL[mt], sb + 18432 + ao);
            }
#pragma unroll
            for (int nt = 0; nt < 2; ++nt) {
                uint32_t bo = bBase + (uint32_t)(nt * 8 * 144 + ks * 32);
                uint32_t bh0, bh1, bl0, bl1;
                ldmx2(bh0, bh1, sb + bo);
#pragma unroll
                for (int mt = 0; mt < 4; ++mt) mma_bf16(acc[mt][nt], AH[mt], bh0, bh1);
#pragma unroll
                for (int mt = 0; mt < 4; ++mt) mma_bf16(acc[mt][nt], AL[mt], bh0, bh1);
                ldmx2(bl0, bl1, sb + bo + 9216);
#pragma unroll
                for (int mt = 0; mt < 4; ++mt) mma_bf16(acc[mt][nt], AH[mt], bl0, bl1);
            }
        }
    }

    int g4 = lane >> 2, t4 = lane & 3;
#pragma unroll
    for (int mt = 0; mt < 4; ++mt) {
#pragma unroll
        for (int nt = 0; nt < 2; ++nt) {
            int co = wm + mt * 16 + g4;
            int px = w0 + wn + nt * 8 + t4 * 2;
            float* op = out + (((size_t)b * CO + co) * H + h) * W + px;
            *reinterpret_cast<float2*>(op) = make_float2(acc[mt][nt][0], acc[mt][nt][1]);
            float* op2 = out + (((size_t)b * CO + co + 8) * H + h) * W + px;
            *reinterpret_cast<float2*>(op2) = make_float2(acc[mt][nt][2], acc[mt][nt][3]);
        }
    }
}

// ---------------------------------------------------------------------------
extern "C" void kernel_launch(void* const* d_in, const int* in_sizes, int n_in,
                              void* d_out, int out_size) {
    const float* x      = (const float*)d_in[0];
    const float* w_p    = (const float*)d_in[1];
    const float* b_p    = (const float*)d_in[2];
    const float* w_m    = (const float*)d_in[3];
    const float* b_m    = (const float*)d_in[4];
    const float* w_conv = (const float*)d_in[5];
    float* out = (float*)d_out;

    cudaFuncSetAttribute(mma_main_kernel, cudaFuncAttributeMaxDynamicSharedMemorySize, SM_TOTAL);
    cudaFuncSetAttribute(conv_mma_kernel, cudaFuncAttributeMaxDynamicSharedMemorySize, SC_TOTAL);

    zero_border_kernel<<<(B * 516 * 32 + 255) / 256, 256>>>();
    prep_weights_kernel<<<720, 256>>>(w_p, w_m, w_conv);
    pad_transpose_kernel<<<dim3(W / 32, C / 32, B * H), dim3(32, 8)>>>(x);
    conv_mma_kernel<<<512, 256, SC_TOTAL>>>();
    off_comb_kernel<<<B * H, 128>>>(b_p, b_m);
    mma_main_kernel<<<512, 256, SM_TOTAL>>>(out);
}

// round 9
// speedup vs baseline: 1.2613x; 1.2613x over previous
#include <cuda_runtime.h>
#include <cuda_bf16.h>
#include <math.h>
#include <stdint.h>

// Problem constants
#define B 2
#define C 128
#define H 128
#define W 128
#define HP 130
#define WP 130
#define NPT 9
#define CO 128
#define BHW (B * H * W)

// Scratch (device globals; allocation-free)
__device__ __align__(16) float g_xp[B * HP * WP * C];           // padded NHWC x (~17.3 MB)
__device__ __align__(16) float4 g_gates2[NPT * BHW];            // gates [n][pix] (lt,rb,lb,rt)
__device__ __align__(16) int4   g_offs2 [NPT * BHW];            // corner spatial offsets [n][pix]
__device__ __align__(16) float g_part[27 * BHW];                // offset conv outputs [ch][pix]
// bf16 hi/lo weight tiles:
//   main conv:   9 tiles [tap][co 128][k 128]
//   offset conv: 18 tiles (tap x ci-half) [ch 32(27 pad)][k 64]
__device__ __align__(16) unsigned short g_wA_hi[9 * 16384];
__device__ __align__(16) unsigned short g_wA_lo[9 * 16384];
__device__ __align__(16) unsigned short g_wO_hi[18 * 2048];
__device__ __align__(16) unsigned short g_wO_lo[18 * 2048];

// ---------------------------------------------------------------------------
// PTX helpers (all sm_80-era: no arch-"a" gated instructions)
__device__ __forceinline__ uint32_t smem_u32(const void* p) {
    uint32_t a;
    asm("{ .reg .u64 t; cvta.to.shared.u64 t, %1; cvt.u32.u64 %0, t; }" : "=r"(a) : "l"(p));
    return a;
}
__device__ __forceinline__ void ldmx4(uint32_t* r, uint32_t a) {
    asm volatile("ldmatrix.sync.aligned.m8n8.x4.shared.b16 {%0,%1,%2,%3}, [%4];"
                 : "=r"(r[0]), "=r"(r[1]), "=r"(r[2]), "=r"(r[3]) : "r"(a));
}
__device__ __forceinline__ void ldmx2(uint32_t& r0, uint32_t& r1, uint32_t a) {
    asm volatile("ldmatrix.sync.aligned.m8n8.x2.shared.b16 {%0,%1}, [%2];"
                 : "=r"(r0), "=r"(r1) : "r"(a));
}
__device__ __forceinline__ void mma_bf16(float* c, const uint32_t* a, uint32_t b0, uint32_t b1) {
    asm volatile(
        "mma.sync.aligned.m16n8k16.row.col.f32.bf16.bf16.f32 "
        "{%0,%1,%2,%3}, {%4,%5,%6,%7}, {%8,%9}, {%0,%1,%2,%3};"
        : "+f"(c[0]), "+f"(c[1]), "+f"(c[2]), "+f"(c[3])
        : "r"(a[0]), "r"(a[1]), "r"(a[2]), "r"(a[3]), "r"(b0), "r"(b1));
}
__device__ __forceinline__ void bf16_split(float v, uint16_t& hi, uint16_t& lo) {
    __nv_bfloat16 h = __float2bfloat16_rn(v);
    __nv_bfloat16 l = __float2bfloat16_rn(v - __bfloat162float(h));
    hi = __bfloat16_as_ushort(h);
    lo = __bfloat16_as_ushort(l);
}
__device__ __forceinline__ uint32_t pack2(uint16_t a, uint16_t b) {
    return (uint32_t)a | ((uint32_t)b << 16);
}
__device__ __forceinline__ void cp16(uint32_t dst, const void* src) {
    asm volatile("cp.async.ca.shared.global [%0], [%1], 16;" :: "r"(dst), "l"(src));
}
__device__ __forceinline__ void cp_commit() {
    asm volatile("cp.async.commit_group;" ::: "memory");
}
template <int N>
__device__ __forceinline__ void cp_wait() {
    asm volatile("cp.async.wait_group %0;" :: "n"(N) : "memory");
}

// ---------------------------------------------------------------------------
// Kernel 0: zero only the pad border of g_xp (interior fully overwritten)
__global__ void zero_border_kernel() {
    int i = blockIdx.x * blockDim.x + threadIdx.x;
    if (i >= B * 516 * 32) return;
    int q = i & 31;
    int p = i >> 5;
    int b = p / 516;
    int r = p - b * 516;
    int hh, ww;
    if (r < 130)      { hh = 0;        ww = r; }
    else if (r < 260) { hh = 129;      ww = r - 130; }
    else if (r < 388) { hh = r - 259;  ww = 0; }
    else              { hh = r - 387;  ww = 129; }
    reinterpret_cast<float4*>(g_xp)[((size_t)(b * HP + hh) * WP + ww) * 32 + q] =
        make_float4(0.f, 0.f, 0.f, 0.f);
}

// ---------------------------------------------------------------------------
// Kernel 1: weight re-layouts -> bf16 hi/lo tiles (main [tap][co][k128] + offset conv)
__global__ void prep_weights_kernel(const float* __restrict__ wp,
                                    const float* __restrict__ wm,
                                    const float* __restrict__ wc) {
    const int n_off = 18 * 32 * 64;          // 36864
    const int n_wa  = 9 * 128 * 128;         // 147456
    for (int e = blockIdx.x * blockDim.x + threadIdx.x; e < n_off + n_wa;
         e += gridDim.x * blockDim.x) {
        if (e < n_off) {
            int tile = e >> 11;
            int r = e & 2047;
            int ch = r >> 6;
            int c = r & 63;
            int n = tile >> 1, half = tile & 1;
            int ci = half * 64 + c;
            float v = 0.f;
            if (ch < 18)      v = wp[(ch * C + ci) * 9 + n];
            else if (ch < 27) v = wm[((ch - 18) * C + ci) * 9 + n];
            uint16_t hi, lo;
            bf16_split(v, hi, lo);
            g_wO_hi[e] = hi;
            g_wO_lo[e] = lo;
        } else {
            int t = e - n_off;
            int tap = t >> 14;               // 0..8
            int r = t & 16383;
            int co = r >> 7;
            int k = r & 127;
            float v = wc[(co * C + k) * 9 + tap];
            uint16_t hi, lo;
            bf16_split(v, hi, lo);
            g_wA_hi[t] = hi;
            g_wA_lo[t] = lo;
        }
    }
}

// ---------------------------------------------------------------------------
// Kernel 2: pad + transpose NCHW -> padded NHWC
__global__ void pad_transpose_kernel(const float* __restrict__ x) {
    __shared__ float tile[32][33];
    int w0 = blockIdx.x * 32;
    int c0 = blockIdx.y * 32;
    int bh = blockIdx.z;
    int b = bh >> 7, h = bh & 127;
    int tx = threadIdx.x, ty = threadIdx.y;
#pragma unroll
    for (int r = 0; r < 4; ++r) {
        int ci = c0 + ty + r * 8;
        tile[ty + r * 8][tx] = x[(((size_t)b * C + ci) * H + h) * W + w0 + tx];
    }
    __syncthreads();
#pragma unroll
    for (int r = 0; r < 4; ++r) {
        int w = w0 + ty + r * 8;
        g_xp[(((size_t)b * HP + h + 1) * WP + (w + 1)) * C + c0 + tx] = tile[tx][ty + r * 8];
    }
}

// ---------------------------------------------------------------------------
// Kernel 3a: offset/mask conv via HMMA, tap-shift trick, cp.async W double-buffer,
// ONE barrier per tap. CTA = 27(32) ch x 64 pixels, 256 thr, 2 CTAs/SM (75.5 KB).
#define SC_UROW (66 * 144)              // 9504 B per xp row
#define SC_UHI 0                        // 3 rows hi: 28512
#define SC_ULO (3 * SC_UROW)            // 3 rows lo: 28512
#define SC_W   (6 * SC_UROW)            // W double buffer: 2 x (hi 4608 + lo 4608)
#define SC_TOTAL (SC_W + 2 * 9216)      // 75456 B
__device__ __forceinline__ void stage_wO(uint32_t sb, int buf, int chunk, int tid) {
    uint32_t off = (uint32_t)(SC_W + buf * 9216 + (tid >> 3) * 144 + (tid & 7) * 16);
    cp16(sb + off, reinterpret_cast<const float4*>(g_wO_hi) + chunk * 256 + tid);
    cp16(sb + off + 4608, reinterpret_cast<const float4*>(g_wO_lo) + chunk * 256 + tid);
}
__global__ __launch_bounds__(256, 2) void conv_mma_kernel() {
    extern __shared__ __align__(128) char smem[];
    uint32_t sb = smem_u32(smem);
    int tid = threadIdx.x;
    int wid = tid >> 5, lane = tid & 31;

    int idx = blockIdx.x;
    int b = idx >> 8;
    int h = (idx >> 1) & 127;
    int w0 = (idx & 1) * 64;

    const float4* xb4 = reinterpret_cast<const float4*>(g_xp) + (size_t)b * HP * WP * 32;

    int wm = (wid & 1) * 16;          // ch half
    int wn = (wid >> 1) * 16;         // pixel quarter

    int asel = lane >> 3;
    int aRow = ((asel & 1) << 3) + (lane & 7);
    int aK = (asel >> 1) << 3;
    uint32_t aBase = (uint32_t)((wm + aRow) * 144 + aK * 2);
    uint32_t bPix = (uint32_t)(wn + (lane & 7));
    uint32_t bKoff = (uint32_t)((((lane >> 3) & 1) << 3) * 2);

    float acc[2][4];
#pragma unroll
    for (int nt = 0; nt < 2; ++nt)
#pragma unroll
        for (int j = 0; j < 4; ++j) acc[nt][j] = 0.f;

    for (int half = 0; half < 2; ++half) {
        __syncthreads();   // previous half's MMAs done; U + W buffers reusable

        // prefetch W for tap 0 of this half
        stage_wO(sb, 0, 0 * 2 + half, tid);
        cp_commit();

        // stage U: 3 rows x 66 pixels x 16 float4, hi/lo split
        for (int i = tid; i < 3 * 66 * 16; i += 256) {
            int row = i / (66 * 16);
            int rem = i - row * (66 * 16);
            int pix = rem >> 4;
            int q = rem & 15;
            float4 v = xb4[((size_t)(h + row) * WP + (w0 + pix)) * 32 + half * 16 + q];
            uint16_t hx, lx, hy, ly, hz, lz, hw_, lw_;
            bf16_split(v.x, hx, lx);
            bf16_split(v.y, hy, ly);
            bf16_split(v.z, hz, lz);
            bf16_split(v.w, hw_, lw_);
            uint32_t uoff = (uint32_t)(row * SC_UROW + pix * 144 + q * 8);
            *reinterpret_cast<uint2*>(smem + SC_UHI + uoff) = make_uint2(pack2(hx, hy), pack2(hz, hw_));
            *reinterpret_cast<uint2*>(smem + SC_ULO + uoff) = make_uint2(pack2(lx, ly), pack2(lz, lw_));
        }

#pragma unroll
        for (int tap = 0; tap < 9; ++tap) {
            cp_wait<0>();
            __syncthreads();   // W(tap) visible; all warps done with the other W buffer
            if (tap < 8) {
                stage_wO(sb, (tap + 1) & 1, (tap + 1) * 2 + half, tid);
                cp_commit();
            }
            int dh = tap / 3, dw = tap - dh * 3;
            uint32_t wbase = (uint32_t)(SC_W + (tap & 1) * 9216);
            uint32_t ubase = (uint32_t)(dh * SC_UROW) + (bPix + dw) * 144 + bKoff;
#pragma unroll
            for (int ks = 0; ks < 4; ++ks) {
                uint32_t AH[4], AL[4];
                uint32_t ao = wbase + aBase + (uint32_t)(ks * 32);
                ldmx4(AH, sb + ao);
                ldmx4(AL, sb + 4608 + ao);
#pragma unroll
                for (int nt = 0; nt < 2; ++nt) {
                    uint32_t bo = ubase + (uint32_t)(nt * 8 * 144 + ks * 32);
                    uint32_t bh0, bh1, bl0, bl1;
                    ldmx2(bh0, bh1, sb + SC_UHI + bo);
                    mma_bf16(acc[nt], AH, bh0, bh1);
                    mma_bf16(acc[nt], AL, bh0, bh1);
                    ldmx2(bl0, bl1, sb + SC_ULO + bo);
                    mma_bf16(acc[nt], AH, bl0, bl1);
                }
            }
        }
    }

    int g4 = lane >> 2, t4 = lane & 3;
    int pixbase = (b * H + h) * W + w0;
#pragma unroll
    for (int nt = 0; nt < 2; ++nt) {
        int px = wn + nt * 8 + t4 * 2;
        int ch = wm + g4;
        if (ch < 27)
            *reinterpret_cast<float2*>(&g_part[(size_t)ch * BHW + pixbase + px]) =
                make_float2(acc[nt][0], acc[nt][1]);
        if (ch + 8 < 27)
            *reinterpret_cast<float2*>(&g_part[(size_t)(ch + 8) * BHW + pixbase + px]) =
                make_float2(acc[nt][2], acc[nt][3]);
    }
}

// ---------------------------------------------------------------------------
// Kernel 3b: bias + sigmoid + bilinear gate/index precompute (tap-major layout)
__global__ __launch_bounds__(128) void off_comb_kernel(const float* __restrict__ bp,
                                                       const float* __restrict__ bm) {
    int bh = blockIdx.x;
    int b = bh >> 7, h = bh & 127;
    int w = threadIdx.x;
    int pix = bh * 128 + w;

    float acc[27];
#pragma unroll
    for (int ch = 0; ch < 18; ++ch) acc[ch] = bp[ch] + g_part[(size_t)ch * BHW + pix];
#pragma unroll
    for (int ch = 18; ch < 27; ++ch) acc[ch] = bm[ch - 18] + g_part[(size_t)ch * BHW + pix];

#pragma unroll
    for (int n = 0; n < NPT; ++n) {
        float m = 1.f / (1.f + expf(-acc[18 + n]));
        float px = acc[n]     + (float)(h + 1) + (float)(n / 3 - 1);
        float py = acc[9 + n] + (float)(w + 1) + (float)(n % 3 - 1);
        float fx = floorf(px), fy = floorf(py);
        float qltx = fminf(fmaxf(fx,       0.f), 129.f);
        float qlty = fminf(fmaxf(fy,       0.f), 129.f);
        float qrbx = fminf(fmaxf(fx + 1.f, 0.f), 129.f);
        float qrby = fminf(fmaxf(fy + 1.f, 0.f), 129.f);
        float pxc = fminf(fmaxf(px, 0.f), 129.f);
        float pyc = fminf(fmaxf(py, 0.f), 129.f);
        float ax = 1.f + (qltx - pxc);
        float bx = 1.f - (qrbx - pxc);
        float ay = 1.f + (qlty - pyc);
        float by = 1.f - (qrby - pyc);
        int ilt_x = (int)qltx, ilt_y = (int)qlty;
        int irb_x = (int)qrbx, irb_y = (int)qrby;
        g_gates2[n * BHW + pix] = make_float4(ax * ay * m, bx * by * m, ax * by * m, bx * ay * m);
        g_offs2 [n * BHW + pix] = make_int4(ilt_x * WP + ilt_y, irb_x * WP + irb_y,
                                            ilt_x * WP + irb_y, irb_x * WP + ilt_y);
    }
}

// ---------------------------------------------------------------------------
// Kernel 4: fused gather + bf16-split GEMM on warp-level mma (HMMA).
// CTA = 128 co x 64 pixels, 256 thr, 2 CTAs/SM (104 KB smem).
// K = 1152 as 9 tap-chunks of 128. Warp-cooperative gather: each warp loads
// full 512B corner rows (4 wf @ 128B useful). W staged via cp.async per chunk.
#define SMW_HI 0
#define SMW_LO 34816
#define SMU_HI 69632
#define SMU_LO 87040
#define SM_TOTAL 104448
__global__ __launch_bounds__(256, 2) void mma_main_kernel(float* __restrict__ out) {
    extern __shared__ __align__(128) char smem[];
    uint32_t sb = smem_u32(smem);
    int tid = threadIdx.x;
    int wid = tid >> 5, lane = tid & 31;

    int idx = blockIdx.x;
    int b = idx >> 8;
    int h = (idx >> 1) & 127;
    int w0 = (idx & 1) * 64;
    int gbase = (b * H + h) * W + w0;

    const float4* xb4 = reinterpret_cast<const float4*>(g_xp) + (size_t)b * HP * WP * 32;

    int wm = (wid & 1) * 64;
    int wn = (wid >> 1) * 16;

    int asel = lane >> 3;
    int aRow = ((asel & 1) << 3) + (lane & 7);
    int aK = (asel >> 1) << 3;
    uint32_t aBase = (uint32_t)((wm + aRow) * 272 + aK * 2);
    uint32_t bBase = (uint32_t)((wn + (lane & 7)) * 272 + (((lane >> 3) & 1) << 3) * 2);

    float acc[4][2][4];
#pragma unroll
    for (int mt = 0; mt < 4; ++mt)
#pragma unroll
        for (int nt = 0; nt < 2; ++nt)
#pragma unroll
            for (int j = 0; j < 4; ++j) acc[mt][nt][j] = 0.f;

    for (int tap = 0; tap < 9; ++tap) {
        __syncthreads();   // U + W free (prev chunk's MMAs done)

        // stage W tile [128co][128k] hi+lo via cp.async (rows padded to 272B)
        {
            const float4* ah = reinterpret_cast<const float4*>(g_wA_hi) + tap * 2048;
            const float4* al = reinterpret_cast<const float4*>(g_wA_lo) + tap * 2048;
#pragma unroll
            for (int i = 0; i < 8; ++i) {
                int e = tid + i * 256;
                uint32_t off = (uint32_t)((e >> 4) * 272 + (e & 15) * 16);
                cp16(sb + SMW_HI + off, ah + e);
                cp16(sb + SMW_LO + off, al + e);
            }
            cp_commit();
        }

        // warp-cooperative gather: warp owns 8 pixels; 32 lanes = full 512B corner row
#pragma unroll
        for (int p = 0; p < 8; ++p) {
            int pix = wid * 8 + p;
            float4 g = g_gates2[tap * BHW + gbase + pix];
            int4  o = g_offs2 [tap * BHW + gbase + pix];
            float4 v0 = xb4[(size_t)o.x * 32 + lane];
            float4 v1 = xb4[(size_t)o.y * 32 + lane];
            float4 v2 = xb4[(size_t)o.z * 32 + lane];
            float4 v3 = xb4[(size_t)o.w * 32 + lane];
            float4 v;
            v.x = fmaf(g.w, v3.x, fmaf(g.z, v2.x, fmaf(g.y, v1.x, g.x * v0.x)));
            v.y = fmaf(g.w, v3.y, fmaf(g.z, v2.y, fmaf(g.y, v1.y, g.x * v0.y)));
            v.z = fmaf(g.w, v3.z, fmaf(g.z, v2.z, fmaf(g.y, v1.z, g.x * v0.z)));
            v.w = fmaf(g.w, v3.w, fmaf(g.z, v2.w, fmaf(g.y, v1.w, g.x * v0.w)));

            uint16_t hx, lx, hy, ly, hz, lz, hw_, lw_;
            bf16_split(v.x, hx, lx);
            bf16_split(v.y, hy, ly);
            bf16_split(v.z, hz, lz);
            bf16_split(v.w, hw_, lw_);

            uint32_t uoff = (uint32_t)(pix * 272 + lane * 8);
            *reinterpret_cast<uint2*>(smem + SMU_HI + uoff) = make_uint2(pack2(hx, hy), pack2(hz, hw_));
            *reinterpret_cast<uint2*>(smem + SMU_LO + uoff) = make_uint2(pack2(lx, ly), pack2(lz, lw_));
        }

        cp_wait<0>();
        __syncthreads();

        // HMMA: 8 k-steps of 16
#pragma unroll
        for (int ks = 0; ks < 8; ++ks) {
            uint32_t AH[4][4], AL[4][4];
#pragma unroll
            for (int mt = 0; mt < 4; ++mt) {
                uint32_t ao = aBase + (uint32_t)(mt * 16 * 272 + ks * 32);
                ldmx4(AH[mt], sb + SMW_HI + ao);
                ldmx4(AL[mt], sb + SMW_LO + ao);
            }
#pragma unroll
            for (int nt = 0; nt < 2; ++nt) {
                uint32_t bo = bBase + (uint32_t)(nt * 8 * 272 + ks * 32);
                uint32_t bh0, bh1, bl0, bl1;
                ldmx2(bh0, bh1, sb + SMU_HI + bo);
#pragma unroll
                for (int mt = 0; mt < 4; ++mt) mma_bf16(acc[mt][nt], AH[mt], bh0, bh1);
#pragma unroll
                for (int mt = 0; mt < 4; ++mt) mma_bf16(acc[mt][nt], AL[mt], bh0, bh1);
                ldmx2(bl0, bl1, sb + SMU_LO + bo);
#pragma unroll
                for (int mt = 0; mt < 4; ++mt) mma_bf16(acc[mt][nt], AH[mt], bl0, bl1);
            }
        }
    }

    int g4 = lane >> 2, t4 = lane & 3;
#pragma unroll
    for (int mt = 0; mt < 4; ++mt) {
#pragma unroll
        for (int nt = 0; nt < 2; ++nt) {
            int co = wm + mt * 16 + g4;
            int px = w0 + wn + nt * 8 + t4 * 2;
            float* op = out + (((size_t)b * CO + co) * H + h) * W + px;
            *reinterpret_cast<float2*>(op) = make_float2(acc[mt][nt][0], acc[mt][nt][1]);
            float* op2 = out + (((size_t)b * CO + co + 8) * H + h) * W + px;
            *reinterpret_cast<float2*>(op2) = make_float2(acc[mt][nt][2], acc[mt][nt][3]);
        }
    }
}

// ---------------------------------------------------------------------------
extern "C" void kernel_launch(void* const* d_in, const int* in_sizes, int n_in,
                              void* d_out, int out_size) {
    const float* x      = (const float*)d_in[0];
    const float* w_p    = (const float*)d_in[1];
    const float* b_p    = (const float*)d_in[2];
    const float* w_m    = (const float*)d_in[3];
    const float* b_m    = (const float*)d_in[4];
    const float* w_conv = (const float*)d_in[5];
    float* out = (float*)d_out;

    cudaFuncSetAttribute(mma_main_kernel, cudaFuncAttributeMaxDynamicSharedMemorySize, SM_TOTAL);
    cudaFuncSetAttribute(conv_mma_kernel, cudaFuncAttributeMaxDynamicSharedMemorySize, SC_TOTAL);

    zero_border_kernel<<<(B * 516 * 32 + 255) / 256, 256>>>();
    prep_weights_kernel<<<720, 256>>>(w_p, w_m, w_conv);
    pad_transpose_kernel<<<dim3(W / 32, C / 32, B * H), dim3(32, 8)>>>(x);
    conv_mma_kernel<<<512, 256, SC_TOTAL>>>();
    off_comb_kernel<<<B * H, 128>>>(b_p, b_m);
    mma_main_kernel<<<512, 256, SM_TOTAL>>>(out);
}

// round 10
// speedup vs baseline: 1.3076x; 1.0367x over previous
#include <cuda_runtime.h>
#include <cuda_bf16.h>
#include <math.h>
#include <stdint.h>

// Problem constants
#define B 2
#define C 128
#define H 128
#define W 128
#define HP 130
#define WP 130
#define NPT 9
#define CO 128
#define BHW (B * H * W)

// Scratch (device globals; allocation-free)
__device__ __align__(16) float g_xp[B * HP * WP * C];           // padded NHWC x (~17.3 MB)
__device__ __align__(16) float4 g_gates2[NPT * BHW];            // gates [n][pix] (lt,rb,lb,rt)
__device__ __align__(16) int4   g_offs2 [NPT * BHW];            // corner spatial offsets [n][pix]
__device__ __align__(16) float g_part[27 * BHW];                // offset conv outputs [ch][pix]
// bf16 hi/lo weight tiles, 18 tiles (tap x ci-half):
//   main conv:   [co 128][k 64]
//   offset conv: [ch 32(27 pad)][k 64]
__device__ __align__(16) unsigned short g_wA_hi[18 * 8192];
__device__ __align__(16) unsigned short g_wA_lo[18 * 8192];
__device__ __align__(16) unsigned short g_wO_hi[18 * 2048];
__device__ __align__(16) unsigned short g_wO_lo[18 * 2048];

// ---------------------------------------------------------------------------
// PTX helpers (all sm_80-era: no arch-"a" gated instructions)
__device__ __forceinline__ uint32_t smem_u32(const void* p) {
    uint32_t a;
    asm("{ .reg .u64 t; cvta.to.shared.u64 t, %1; cvt.u32.u64 %0, t; }" : "=r"(a) : "l"(p));
    return a;
}
__device__ __forceinline__ void ldmx4(uint32_t* r, uint32_t a) {
    asm volatile("ldmatrix.sync.aligned.m8n8.x4.shared.b16 {%0,%1,%2,%3}, [%4];"
                 : "=r"(r[0]), "=r"(r[1]), "=r"(r[2]), "=r"(r[3]) : "r"(a));
}
__device__ __forceinline__ void ldmx2(uint32_t& r0, uint32_t& r1, uint32_t a) {
    asm volatile("ldmatrix.sync.aligned.m8n8.x2.shared.b16 {%0,%1}, [%2];"
                 : "=r"(r0), "=r"(r1) : "r"(a));
}
__device__ __forceinline__ void mma_bf16(float* c, const uint32_t* a, uint32_t b0, uint32_t b1) {
    asm volatile(
        "mma.sync.aligned.m16n8k16.row.col.f32.bf16.bf16.f32 "
        "{%0,%1,%2,%3}, {%4,%5,%6,%7}, {%8,%9}, {%0,%1,%2,%3};"
        : "+f"(c[0]), "+f"(c[1]), "+f"(c[2]), "+f"(c[3])
        : "r"(a[0]), "r"(a[1]), "r"(a[2]), "r"(a[3]), "r"(b0), "r"(b1));
}
__device__ __forceinline__ void bf16_split(float v, uint16_t& hi, uint16_t& lo) {
    __nv_bfloat16 h = __float2bfloat16_rn(v);
    __nv_bfloat16 l = __float2bfloat16_rn(v - __bfloat162float(h));
    hi = __bfloat16_as_ushort(h);
    lo = __bfloat16_as_ushort(l);
}
__device__ __forceinline__ uint32_t pack2(uint16_t a, uint16_t b) {
    return (uint32_t)a | ((uint32_t)b << 16);
}
__device__ __forceinline__ void cp16(uint32_t dst, const void* src) {
    asm volatile("cp.async.ca.shared.global [%0], [%1], 16;" :: "r"(dst), "l"(src));
}
__device__ __forceinline__ void cp_commit() {
    asm volatile("cp.async.commit_group;" ::: "memory");
}
template <int N>
__device__ __forceinline__ void cp_wait() {
    asm volatile("cp.async.wait_group %0;" :: "n"(N) : "memory");
}

// ---------------------------------------------------------------------------
// Kernel 0: zero only the pad border of g_xp (interior fully overwritten)
__global__ void zero_border_kernel() {
    int i = blockIdx.x * blockDim.x + threadIdx.x;
    if (i >= B * 516 * 32) return;
    int q = i & 31;
    int p = i >> 5;
    int b = p / 516;
    int r = p - b * 516;
    int hh, ww;
    if (r < 130)      { hh = 0;        ww = r; }
    else if (r < 260) { hh = 129;      ww = r - 130; }
    else if (r < 388) { hh = r - 259;  ww = 0; }
    else              { hh = r - 387;  ww = 129; }
    reinterpret_cast<float4*>(g_xp)[((size_t)(b * HP + hh) * WP + ww) * 32 + q] =
        make_float4(0.f, 0.f, 0.f, 0.f);
}

// ---------------------------------------------------------------------------
// Kernel 1: weight re-layouts -> bf16 hi/lo tiles (main + offset conv, 18 tiles each)
__global__ void prep_weights_kernel(const float* __restrict__ wp,
                                    const float* __restrict__ wm,
                                    const float* __restrict__ wc) {
    const int n_off = 18 * 32 * 64;          // 36864
    const int n_wa  = 18 * 128 * 64;         // 147456
    for (int e = blockIdx.x * blockDim.x + threadIdx.x; e < n_off + n_wa;
         e += gridDim.x * blockDim.x) {
        if (e < n_off) {
            int tile = e >> 11;
            int r = e & 2047;
            int ch = r >> 6;
            int c = r & 63;
            int n = tile >> 1, half = tile & 1;
            int ci = half * 64 + c;
            float v = 0.f;
            if (ch < 18)      v = wp[(ch * C + ci) * 9 + n];
            else if (ch < 27) v = wm[((ch - 18) * C + ci) * 9 + n];
            uint16_t hi, lo;
            bf16_split(v, hi, lo);
            g_wO_hi[e] = hi;
            g_wO_lo[e] = lo;
        } else {
            int t = e - n_off;
            int tile = t >> 13;              // tap*2 + half
            int r = t & 8191;
            int co = r >> 6;
            int c = r & 63;
            int n = tile >> 1, half = tile & 1;
            int ci = half * 64 + c;
            float v = wc[(co * C + ci) * 9 + n];
            uint16_t hi, lo;
            bf16_split(v, hi, lo);
            g_wA_hi[t] = hi;
            g_wA_lo[t] = lo;
        }
    }
}

// ---------------------------------------------------------------------------
// Kernel 2: pad + transpose NCHW -> padded NHWC
__global__ void pad_transpose_kernel(const float* __restrict__ x) {
    __shared__ float tile[32][33];
    int w0 = blockIdx.x * 32;
    int c0 = blockIdx.y * 32;
    int bh = blockIdx.z;
    int b = bh >> 7, h = bh & 127;
    int tx = threadIdx.x, ty = threadIdx.y;
#pragma unroll
    for (int r = 0; r < 4; ++r) {
        int ci = c0 + ty + r * 8;
        tile[ty + r * 8][tx] = x[(((size_t)b * C + ci) * H + h) * W + w0 + tx];
    }
    __syncthreads();
#pragma unroll
    for (int r = 0; r < 4; ++r) {
        int w = w0 + ty + r * 8;
        g_xp[(((size_t)b * HP + h + 1) * WP + (w + 1)) * C + c0 + tx] = tile[tx][ty + r * 8];
    }
}

// ---------------------------------------------------------------------------
// Kernel 3a: offset/mask conv via HMMA, tap-shift trick, cp.async W double-buffer,
// ONE barrier per tap. CTA = 27(32) ch x 64 pixels, 256 thr, 2 CTAs/SM (75.5 KB).
#define SC_UROW (66 * 144)              // 9504 B per xp row
#define SC_UHI 0                        // 3 rows hi: 28512
#define SC_ULO (3 * SC_UROW)            // 3 rows lo: 28512
#define SC_W   (6 * SC_UROW)            // W double buffer: 2 x (hi 4608 + lo 4608)
#define SC_TOTAL (SC_W + 2 * 9216)      // 75456 B
__device__ __forceinline__ void stage_wO(uint32_t sb, int buf, int chunk, int tid) {
    uint32_t off = (uint32_t)(SC_W + buf * 9216 + (tid >> 3) * 144 + (tid & 7) * 16);
    cp16(sb + off, reinterpret_cast<const float4*>(g_wO_hi) + chunk * 256 + tid);
    cp16(sb + off + 4608, reinterpret_cast<const float4*>(g_wO_lo) + chunk * 256 + tid);
}
__global__ __launch_bounds__(256, 2) void conv_mma_kernel() {
    extern __shared__ __align__(128) char smem[];
    uint32_t sb = smem_u32(smem);
    int tid = threadIdx.x;
    int wid = tid >> 5, lane = tid & 31;

    int idx = blockIdx.x;
    int b = idx >> 8;
    int h = (idx >> 1) & 127;
    int w0 = (idx & 1) * 64;

    const float4* xb4 = reinterpret_cast<const float4*>(g_xp) + (size_t)b * HP * WP * 32;

    int wm = (wid & 1) * 16;          // ch half
    int wn = (wid >> 1) * 16;         // pixel quarter

    int asel = lane >> 3;
    int aRow = ((asel & 1) << 3) + (lane & 7);
    int aK = (asel >> 1) << 3;
    uint32_t aBase = (uint32_t)((wm + aRow) * 144 + aK * 2);
    uint32_t bPix = (uint32_t)(wn + (lane & 7));
    uint32_t bKoff = (uint32_t)((((lane >> 3) & 1) << 3) * 2);

    float acc[2][4];
#pragma unroll
    for (int nt = 0; nt < 2; ++nt)
#pragma unroll
        for (int j = 0; j < 4; ++j) acc[nt][j] = 0.f;

    for (int half = 0; half < 2; ++half) {
        __syncthreads();   // previous half's MMAs done; U + W buffers reusable

        // prefetch W for tap 0 of this half
        stage_wO(sb, 0, 0 * 2 + half, tid);
        cp_commit();

        // stage U: 3 rows x 66 pixels x 16 float4, hi/lo split
        for (int i = tid; i < 3 * 66 * 16; i += 256) {
            int row = i / (66 * 16);
            int rem = i - row * (66 * 16);
            int pix = rem >> 4;
            int q = rem & 15;
            float4 v = xb4[((size_t)(h + row) * WP + (w0 + pix)) * 32 + half * 16 + q];
            uint16_t hx, lx, hy, ly, hz, lz, hw_, lw_;
            bf16_split(v.x, hx, lx);
            bf16_split(v.y, hy, ly);
            bf16_split(v.z, hz, lz);
            bf16_split(v.w, hw_, lw_);
            uint32_t uoff = (uint32_t)(row * SC_UROW + pix * 144 + q * 8);
            *reinterpret_cast<uint2*>(smem + SC_UHI + uoff) = make_uint2(pack2(hx, hy), pack2(hz, hw_));
            *reinterpret_cast<uint2*>(smem + SC_ULO + uoff) = make_uint2(pack2(lx, ly), pack2(lz, lw_));
        }

#pragma unroll
        for (int tap = 0; tap < 9; ++tap) {
            cp_wait<0>();
            __syncthreads();   // W(tap) visible; all warps done with the other W buffer
            if (tap < 8) {
                stage_wO(sb, (tap + 1) & 1, (tap + 1) * 2 + half, tid);
                cp_commit();
            }
            int dh = tap / 3, dw = tap - dh * 3;
            uint32_t wbase = (uint32_t)(SC_W + (tap & 1) * 9216);
            uint32_t ubase = (uint32_t)(dh * SC_UROW) + (bPix + dw) * 144 + bKoff;
#pragma unroll
            for (int ks = 0; ks < 4; ++ks) {
                uint32_t AH[4], AL[4];
                uint32_t ao = wbase + aBase + (uint32_t)(ks * 32);
                ldmx4(AH, sb + ao);
                ldmx4(AL, sb + 4608 + ao);
#pragma unroll
                for (int nt = 0; nt < 2; ++nt) {
                    uint32_t bo = ubase + (uint32_t)(nt * 8 * 144 + ks * 32);
                    uint32_t bh0, bh1, bl0, bl1;
                    ldmx2(bh0, bh1, sb + SC_UHI + bo);
                    mma_bf16(acc[nt], AH, bh0, bh1);
                    mma_bf16(acc[nt], AL, bh0, bh1);
                    ldmx2(bl0, bl1, sb + SC_ULO + bo);
                    mma_bf16(acc[nt], AH, bl0, bl1);
                }
            }
        }
    }

    int g4 = lane >> 2, t4 = lane & 3;
    int pixbase = (b * H + h) * W + w0;
#pragma unroll
    for (int nt = 0; nt < 2; ++nt) {
        int px = wn + nt * 8 + t4 * 2;
        int ch = wm + g4;
        if (ch < 27)
            *reinterpret_cast<float2*>(&g_part[(size_t)ch * BHW + pixbase + px]) =
                make_float2(acc[nt][0], acc[nt][1]);
        if (ch + 8 < 27)
            *reinterpret_cast<float2*>(&g_part[(size_t)(ch + 8) * BHW + pixbase + px]) =
                make_float2(acc[nt][2], acc[nt][3]);
    }
}

// ---------------------------------------------------------------------------
// Kernel 3b: bias + sigmoid + bilinear gate/index precompute (tap-major layout)
__global__ __launch_bounds__(128) void off_comb_kernel(const float* __restrict__ bp,
                                                       const float* __restrict__ bm) {
    int bh = blockIdx.x;
    int b = bh >> 7, h = bh & 127;
    int w = threadIdx.x;
    int pix = bh * 128 + w;

    float acc[27];
#pragma unroll
    for (int ch = 0; ch < 18; ++ch) acc[ch] = bp[ch] + g_part[(size_t)ch * BHW + pix];
#pragma unroll
    for (int ch = 18; ch < 27; ++ch) acc[ch] = bm[ch - 18] + g_part[(size_t)ch * BHW + pix];

#pragma unroll
    for (int n = 0; n < NPT; ++n) {
        float m = 1.f / (1.f + expf(-acc[18 + n]));
        float px = acc[n]     + (float)(h + 1) + (float)(n / 3 - 1);
        float py = acc[9 + n] + (float)(w + 1) + (float)(n % 3 - 1);
        float fx = floorf(px), fy = floorf(py);
        float qltx = fminf(fmaxf(fx,       0.f), 129.f);
        float qlty = fminf(fmaxf(fy,       0.f), 129.f);
        float qrbx = fminf(fmaxf(fx + 1.f, 0.f), 129.f);
        float qrby = fminf(fmaxf(fy + 1.f, 0.f), 129.f);
        float pxc = fminf(fmaxf(px, 0.f), 129.f);
        float pyc = fminf(fmaxf(py, 0.f), 129.f);
        float ax = 1.f + (qltx - pxc);
        float bx = 1.f - (qrbx - pxc);
        float ay = 1.f + (qlty - pyc);
        float by = 1.f - (qrby - pyc);
        int ilt_x = (int)qltx, ilt_y = (int)qlty;
        int irb_x = (int)qrbx, irb_y = (int)qrby;
        g_gates2[n * BHW + pix] = make_float4(ax * ay * m, bx * by * m, ax * by * m, bx * ay * m);
        g_offs2 [n * BHW + pix] = make_int4(ilt_x * WP + ilt_y, irb_x * WP + irb_y,
                                            ilt_x * WP + irb_y, irb_x * WP + ilt_y);
    }
}

// ---------------------------------------------------------------------------
// Kernel 4: fused gather + bf16-split GEMM on warp-level mma (HMMA).
// CTA = 128 co x 128 pixels (one full image row), 256 thr, 2 CTAs/SM (73.7 KB).
// K = 1152 as 18 chunks of 64 (tap x ci-half) -> halves per-pixel A-tile LDS traffic.
// Warp layout 2M x 4N (warp tile 64co x 32pix); B fragments cached per k-step.
#define SMW_HI 0
#define SMW_LO 18432
#define SMU_HI 36864
#define SMU_LO 55296
#define SM_TOTAL 73728
__global__ __launch_bounds__(256, 2) void mma_main_kernel(float* __restrict__ out) {
    extern __shared__ __align__(128) char smem[];
    uint32_t sb = smem_u32(smem);
    int tid = threadIdx.x;
    int wid = tid >> 5, lane = tid & 31;

    int idx = blockIdx.x;              // 0..255 = b*H + h
    int b = idx >> 7, h = idx & 127;
    int gbase = idx * 128;             // pixel base (full row)

    const float4* xb4 = reinterpret_cast<const float4*>(g_xp) + (size_t)b * HP * WP * 32;

    int wm = (wid & 1) * 64;           // co half
    int wn = (wid >> 1) * 32;          // pixel quarter (32 pix)

    int asel = lane >> 3;
    int aRow = ((asel & 1) << 3) + (lane & 7);
    int aK = (asel >> 1) << 3;
    uint32_t aBase = (uint32_t)((wm + aRow) * 144 + aK * 2);
    uint32_t bBase = (uint32_t)((wn + (lane & 7)) * 144 + (((lane >> 3) & 1) << 3) * 2);

    // gather mapping: warp owns 16 pixels; half-warp per pixel (16 lanes = 64 ci)
    int gp = wid * 16 + (lane >> 4);   // base pixel (+2*pp)
    int lq = lane & 15;                // ci quad within the 64-ci half

    float acc[4][4][4];
#pragma unroll
    for (int mt = 0; mt < 4; ++mt)
#pragma unroll
        for (int nt = 0; nt < 4; ++nt)
#pragma unroll
            for (int j = 0; j < 4; ++j) acc[mt][nt][j] = 0.f;

    for (int chunk = 0; chunk < 18; ++chunk) {
        int tap = chunk >> 1, half = chunk & 1;
        __syncthreads();   // U + W free (prev chunk's MMAs done)

        // stage W tile [128co][64k] hi+lo via cp.async (rows padded to 144B)
        {
            const float4* ah = reinterpret_cast<const float4*>(g_wA_hi) + chunk * 1024;
            const float4* al = reinterpret_cast<const float4*>(g_wA_lo) + chunk * 1024;
#pragma unroll
            for (int i = 0; i < 4; ++i) {
                int e = tid + i * 256;
                uint32_t off = (uint32_t)((e >> 3) * 144 + (e & 7) * 16);
                cp16(sb + SMW_HI + off, ah + e);
                cp16(sb + SMW_LO + off, al + e);
            }
            cp_commit();
        }

        // gather: 8 pixel-pairs per warp; 16 lanes cover one corner's 64-ci row
        const float4* xh = xb4 + half * 16;
#pragma unroll
        for (int pp = 0; pp < 8; ++pp) {
            int pix = gp + pp * 2;
            float4 g = g_gates2[tap * BHW + gbase + pix];
            int4  o = g_offs2 [tap * BHW + gbase + pix];
            float4 v0 = xh[(size_t)o.x * 32 + lq];
            float4 v1 = xh[(size_t)o.y * 32 + lq];
            float4 v2 = xh[(size_t)o.z * 32 + lq];
            float4 v3 = xh[(size_t)o.w * 32 + lq];
            float4 v;
            v.x = fmaf(g.w, v3.x, fmaf(g.z, v2.x, fmaf(g.y, v1.x, g.x * v0.x)));
            v.y = fmaf(g.w, v3.y, fmaf(g.z, v2.y, fmaf(g.y, v1.y, g.x * v0.y)));
            v.z = fmaf(g.w, v3.z, fmaf(g.z, v2.z, fmaf(g.y, v1.z, g.x * v0.z)));
            v.w = fmaf(g.w, v3.w, fmaf(g.z, v2.w, fmaf(g.y, v1.w, g.x * v0.w)));

            uint16_t hx, lx, hy, ly, hz, lz, hw_, lw_;
            bf16_split(v.x, hx, lx);
            bf16_split(v.y, hy, ly);
            bf16_split(v.z, hz, lz);
            bf16_split(v.w, hw_, lw_);

            uint32_t uoff = (uint32_t)(pix * 144 + lq * 8);
            *reinterpret_cast<uint2*>(smem + SMU_HI + uoff) = make_uint2(pack2(hx, hy), pack2(hz, hw_));
            *reinterpret_cast<uint2*>(smem + SMU_LO + uoff) = make_uint2(pack2(lx, ly), pack2(lz, lw_));
        }

        cp_wait<0>();
        __syncthreads();

        // HMMA: 4 k-steps of 16; B fragments cached, A streamed per mt
#pragma unroll
        for (int ks = 0; ks < 4; ++ks) {
            uint32_t BH[4][2], BL[4][2];
#pragma unroll
            for (int nt = 0; nt < 4; ++nt) {
                uint32_t bo = bBase + (uint32_t)(nt * 8 * 144 + ks * 32);
                ldmx2(BH[nt][0], BH[nt][1], sb + SMU_HI + bo);
                ldmx2(BL[nt][0], BL[nt][1], sb + SMU_LO + bo);
            }
#pragma unroll
            for (int mt = 0; mt < 4; ++mt) {
                uint32_t AH[4], AL[4];
                uint32_t ao = aBase + (uint32_t)(mt * 16 * 144 + ks * 32);
                ldmx4(AH, sb + SMW_HI + ao);
                ldmx4(AL, sb + SMW_LO + ao);
#pragma unroll
                for (int nt = 0; nt < 4; ++nt) {
                    mma_bf16(acc[mt][nt], AH, BH[nt][0], BH[nt][1]);
                    mma_bf16(acc[mt][nt], AL, BH[nt][0], BH[nt][1]);
                    mma_bf16(acc[mt][nt], AH, BL[nt][0], BL[nt][1]);
                }
            }
        }
    }

    int g4 = lane >> 2, t4 = lane & 3;
#pragma unroll
    for (int mt = 0; mt < 4; ++mt) {
#pragma unroll
        for (int nt = 0; nt < 4; ++nt) {
            int co = wm + mt * 16 + g4;
            int px = wn + nt * 8 + t4 * 2;
            float* op = out + (((size_t)b * CO + co) * H + h) * W + px;
            *reinterpret_cast<float2*>(op) = make_float2(acc[mt][nt][0], acc[mt][nt][1]);
            float* op2 = out + (((size_t)b * CO + co + 8) * H + h) * W + px;
            *reinterpret_cast<float2*>(op2) = make_float2(acc[mt][nt][2], acc[mt][nt][3]);
        }
    }
}

// ---------------------------------------------------------------------------
extern "C" void kernel_launch(void* const* d_in, const int* in_sizes, int n_in,
                              void* d_out, int out_size) {
    const float* x      = (const float*)d_in[0];
    const float* w_p    = (const float*)d_in[1];
    const float* b_p    = (const float*)d_in[2];
    const float* w_m    = (const float*)d_in[3];
    const float* b_m    = (const float*)d_in[4];
    const float* w_conv = (const float*)d_in[5];
    float* out = (float*)d_out;

    cudaFuncSetAttribute(mma_main_kernel, cudaFuncAttributeMaxDynamicSharedMemorySize, SM_TOTAL);
    cudaFuncSetAttribute(conv_mma_kernel, cudaFuncAttributeMaxDynamicSharedMemorySize, SC_TOTAL);

    zero_border_kernel<<<(B * 516 * 32 + 255) / 256, 256>>>();
    prep_weights_kernel<<<720, 256>>>(w_p, w_m, w_conv);
    pad_transpose_kernel<<<dim3(W / 32, C / 32, B * H), dim3(32, 8)>>>(x);
    conv_mma_kernel<<<512, 256, SC_TOTAL>>>();
    off_comb_kernel<<<B * H, 128>>>(b_p, b_m);
    mma_main_kernel<<<B * H, 256, SM_TOTAL>>>(out);
}

// round 11
// speedup vs baseline: 1.4063x; 1.0755x over previous
#include <cuda_runtime.h>
#include <cuda_bf16.h>
#include <math.h>
#include <stdint.h>

// Problem constants
#define B 2
#define C 128
#define H 128
#define W 128
#define HP 130
#define WP 130
#define NPT 9
#define CO 128
#define BHW (B * H * W)

// Scratch (device globals; allocation-free)
__device__ __align__(16) float g_xp[B * HP * WP * C];           // padded NHWC x (~17.3 MB)
__device__ __align__(16) float4 g_gates2[NPT * BHW];            // gates [n][pix] (lt,rb,lb,rt)
__device__ __align__(16) int4   g_offs2 [NPT * BHW];            // corner spatial offsets [n][pix]
// bf16 hi/lo weight tiles, 18 tiles (tap x ci-half):
//   main conv:   [co 128][k 64]
//   offset conv: [ch 32(27 pad)][k 64]
__device__ __align__(16) unsigned short g_wA_hi[18 * 8192];
__device__ __align__(16) unsigned short g_wA_lo[18 * 8192];
__device__ __align__(16) unsigned short g_wO_hi[18 * 2048];
__device__ __align__(16) unsigned short g_wO_lo[18 * 2048];

// ---------------------------------------------------------------------------
// PTX helpers (all sm_80-era: no arch-"a" gated instructions)
__device__ __forceinline__ uint32_t smem_u32(const void* p) {
    uint32_t a;
    asm("{ .reg .u64 t; cvta.to.shared.u64 t, %1; cvt.u32.u64 %0, t; }" : "=r"(a) : "l"(p));
    return a;
}
__device__ __forceinline__ void ldmx4(uint32_t* r, uint32_t a) {
    asm volatile("ldmatrix.sync.aligned.m8n8.x4.shared.b16 {%0,%1,%2,%3}, [%4];"
                 : "=r"(r[0]), "=r"(r[1]), "=r"(r[2]), "=r"(r[3]) : "r"(a));
}
__device__ __forceinline__ void mma_bf16(float* c, const uint32_t* a, uint32_t b0, uint32_t b1) {
    asm volatile(
        "mma.sync.aligned.m16n8k16.row.col.f32.bf16.bf16.f32 "
        "{%0,%1,%2,%3}, {%4,%5,%6,%7}, {%8,%9}, {%0,%1,%2,%3};"
        : "+f"(c[0]), "+f"(c[1]), "+f"(c[2]), "+f"(c[3])
        : "r"(a[0]), "r"(a[1]), "r"(a[2]), "r"(a[3]), "r"(b0), "r"(b1));
}
__device__ __forceinline__ void bf16_split(float v, uint16_t& hi, uint16_t& lo) {
    __nv_bfloat16 h = __float2bfloat16_rn(v);
    __nv_bfloat16 l = __float2bfloat16_rn(v - __bfloat162float(h));
    hi = __bfloat16_as_ushort(h);
    lo = __bfloat16_as_ushort(l);
}
__device__ __forceinline__ uint32_t pack2(uint16_t a, uint16_t b) {
    return (uint32_t)a | ((uint32_t)b << 16);
}
__device__ __forceinline__ void cp16(uint32_t dst, const void* src) {
    asm volatile("cp.async.ca.shared.global [%0], [%1], 16;" :: "r"(dst), "l"(src));
}
__device__ __forceinline__ void cp_commit() {
    asm volatile("cp.async.commit_group;" ::: "memory");
}
template <int N>
__device__ __forceinline__ void cp_wait() {
    asm volatile("cp.async.wait_group %0;" :: "n"(N) : "memory");
}

// ---------------------------------------------------------------------------
// Kernel 0: zero only the pad border of g_xp (interior fully overwritten)
__global__ void zero_border_kernel() {
    int i = blockIdx.x * blockDim.x + threadIdx.x;
    if (i >= B * 516 * 32) return;
    int q = i & 31;
    int p = i >> 5;
    int b = p / 516;
    int r = p - b * 516;
    int hh, ww;
    if (r < 130)      { hh = 0;        ww = r; }
    else if (r < 260) { hh = 129;      ww = r - 130; }
    else if (r < 388) { hh = r - 259;  ww = 0; }
    else              { hh = r - 387;  ww = 129; }
    reinterpret_cast<float4*>(g_xp)[((size_t)(b * HP + hh) * WP + ww) * 32 + q] =
        make_float4(0.f, 0.f, 0.f, 0.f);
}

// ---------------------------------------------------------------------------
// Kernel 1: weight re-layouts -> bf16 hi/lo tiles (main + offset conv, 18 tiles each)
__global__ void prep_weights_kernel(const float* __restrict__ wp,
                                    const float* __restrict__ wm,
                                    const float* __restrict__ wc) {
    const int n_off = 18 * 32 * 64;          // 36864
    const int n_wa  = 18 * 128 * 64;         // 147456
    for (int e = blockIdx.x * blockDim.x + threadIdx.x; e < n_off + n_wa;
         e += gridDim.x * blockDim.x) {
        if (e < n_off) {
            int tile = e >> 11;
            int r = e & 2047;
            int ch = r >> 6;
            int c = r & 63;
            int n = tile >> 1, half = tile & 1;
            int ci = half * 64 + c;
            float v = 0.f;
            if (ch < 18)      v = wp[(ch * C + ci) * 9 + n];
            else if (ch < 27) v = wm[((ch - 18) * C + ci) * 9 + n];
            uint16_t hi, lo;
            bf16_split(v, hi, lo);
            g_wO_hi[e] = hi;
            g_wO_lo[e] = lo;
        } else {
            int t = e - n_off;
            int tile = t >> 13;              // tap*2 + half
            int r = t & 8191;
            int co = r >> 6;
            int c = r & 63;
            int n = tile >> 1, half = tile & 1;
            int ci = half * 64 + c;
            float v = wc[(co * C + ci) * 9 + n];
            uint16_t hi, lo;
            bf16_split(v, hi, lo);
            g_wA_hi[t] = hi;
            g_wA_lo[t] = lo;
        }
    }
}

// ---------------------------------------------------------------------------
// Kernel 2: pad + transpose NCHW -> padded NHWC
__global__ void pad_transpose_kernel(const float* __restrict__ x) {
    __shared__ float tile[32][33];
    int w0 = blockIdx.x * 32;
    int c0 = blockIdx.y * 32;
    int bh = blockIdx.z;
    int b = bh >> 7, h = bh & 127;
    int tx = threadIdx.x, ty = threadIdx.y;
#pragma unroll
    for (int r = 0; r < 4; ++r) {
        int ci = c0 + ty + r * 8;
        tile[ty + r * 8][tx] = x[(((size_t)b * C + ci) * H + h) * W + w0 + tx];
    }
    __syncthreads();
#pragma unroll
    for (int r = 0; r < 4; ++r) {
        int w = w0 + ty + r * 8;
        g_xp[(((size_t)b * HP + h + 1) * WP + (w + 1)) * C + c0 + tx] = tile[tx][ty + r * 8];
    }
}

// ---------------------------------------------------------------------------
// Kernel 3: offset/mask conv via HMMA (tap-shift, cp.async W double-buffer)
// FUSED epilogue: bias + sigmoid + bilinear gate/index precompute (no g_part).
// CTA = 27(32) ch x 64 pixels, 256 thr, up to 3 CTAs/SM (75.5 KB).
#define SC_UROW (66 * 144)              // 9504 B per xp row
#define SC_UHI 0                        // 3 rows hi: 28512
#define SC_ULO (3 * SC_UROW)            // 3 rows lo: 28512
#define SC_W   (6 * SC_UROW)            // W double buffer: 2 x (hi 4608 + lo 4608)
#define SC_TOTAL (SC_W + 2 * 9216)      // 75456 B
__device__ __forceinline__ void stage_wO(uint32_t sb, int buf, int chunk, int tid) {
    uint32_t off = (uint32_t)(SC_W + buf * 9216 + (tid >> 3) * 144 + (tid & 7) * 16);
    cp16(sb + off, reinterpret_cast<const float4*>(g_wO_hi) + chunk * 256 + tid);
    cp16(sb + off + 4608, reinterpret_cast<const float4*>(g_wO_lo) + chunk * 256 + tid);
}
__global__ __launch_bounds__(256, 3) void conv_mma_kernel(const float* __restrict__ bp,
                                                          const float* __restrict__ bm) {
    extern __shared__ __align__(128) char smem[];
    uint32_t sb = smem_u32(smem);
    int tid = threadIdx.x;
    int wid = tid >> 5, lane = tid & 31;

    int idx = blockIdx.x;
    int b = idx >> 8;
    int h = (idx >> 1) & 127;
    int w0 = (idx & 1) * 64;

    const float4* xb4 = reinterpret_cast<const float4*>(g_xp) + (size_t)b * HP * WP * 32;

    int wm = (wid & 1) * 16;          // ch half
    int wn = (wid >> 1) * 16;         // pixel quarter

    int asel = lane >> 3;
    int aRow = ((asel & 1) << 3) + (lane & 7);
    int aK = (asel >> 1) << 3;
    uint32_t aBase = (uint32_t)((wm + aRow) * 144 + aK * 2);
    // B ldmx4 lane mapping: lanes 0-7 (nt0,k0), 8-15 (nt0,k8), 16-23 (nt1,k0), 24-31 (nt1,k8)
    int bRow = wn + ((lane >> 4) << 3) + (lane & 7);
    uint32_t bKoff = (uint32_t)(((lane >> 3) & 1) << 4);

    float acc[2][4];
#pragma unroll
    for (int nt = 0; nt < 2; ++nt)
#pragma unroll
        for (int j = 0; j < 4; ++j) acc[nt][j] = 0.f;

    for (int half = 0; half < 2; ++half) {
        __syncthreads();   // previous half's MMAs done; U + W buffers reusable

        // prefetch W for tap 0 of this half
        stage_wO(sb, 0, 0 * 2 + half, tid);
        cp_commit();

        // stage U: 3 rows x 66 pixels x 16 float4, hi/lo split
        for (int i = tid; i < 3 * 66 * 16; i += 256) {
            int row = i / (66 * 16);
            int rem = i - row * (66 * 16);
            int pix = rem >> 4;
            int q = rem & 15;
            float4 v = xb4[((size_t)(h + row) * WP + (w0 + pix)) * 32 + half * 16 + q];
            uint16_t hx, lx, hy, ly, hz, lz, hw_, lw_;
            bf16_split(v.x, hx, lx);
            bf16_split(v.y, hy, ly);
            bf16_split(v.z, hz, lz);
            bf16_split(v.w, hw_, lw_);
            uint32_t uoff = (uint32_t)(row * SC_UROW + pix * 144 + q * 8);
            *reinterpret_cast<uint2*>(smem + SC_UHI + uoff) = make_uint2(pack2(hx, hy), pack2(hz, hw_));
            *reinterpret_cast<uint2*>(smem + SC_ULO + uoff) = make_uint2(pack2(lx, ly), pack2(lz, lw_));
        }

#pragma unroll
        for (int tap = 0; tap < 9; ++tap) {
            cp_wait<0>();
            __syncthreads();   // W(tap) visible; all warps done with the other W buffer
            if (tap < 8) {
                stage_wO(sb, (tap + 1) & 1, (tap + 1) * 2 + half, tid);
                cp_commit();
            }
            int dh = tap / 3, dw = tap - dh * 3;
            uint32_t wbase = (uint32_t)(SC_W + (tap & 1) * 9216);
            uint32_t ubase = (uint32_t)(dh * SC_UROW) + (uint32_t)(bRow + dw) * 144 + bKoff;
#pragma unroll
            for (int ks = 0; ks < 4; ++ks) {
                uint32_t AH[4], AL[4];
                uint32_t ao = wbase + aBase + (uint32_t)(ks * 32);
                ldmx4(AH, sb + ao);
                ldmx4(AL, sb + 4608 + ao);
                uint32_t bo = ubase + (uint32_t)(ks * 32);
                uint32_t BH[4], BL[4];
                ldmx4(BH, sb + SC_UHI + bo);
                ldmx4(BL, sb + SC_ULO + bo);
                mma_bf16(acc[0], AH, BH[0], BH[1]);
                mma_bf16(acc[0], AL, BH[0], BH[1]);
                mma_bf16(acc[0], AH, BL[0], BL[1]);
                mma_bf16(acc[1], AH, BH[2], BH[3]);
                mma_bf16(acc[1], AL, BH[2], BH[3]);
                mma_bf16(acc[1], AH, BL[2], BL[3]);
            }
        }
    }

    // ---- fused epilogue: exchange acc through smem, compute gates/offs ----
    __syncthreads();   // all MMAs (U reads) done; safe to reuse smem
    float* sacc = reinterpret_cast<float*>(smem);   // [32 ch][64 pix]
    {
        int g4 = lane >> 2, t4 = lane & 3;
#pragma unroll
        for (int nt = 0; nt < 2; ++nt) {
            int px = wn + nt * 8 + t4 * 2;
            int ch = wm + g4;
            *reinterpret_cast<float2*>(&sacc[ch * 64 + px]) = make_float2(acc[nt][0], acc[nt][1]);
            *reinterpret_cast<float2*>(&sacc[(ch + 8) * 64 + px]) = make_float2(acc[nt][2], acc[nt][3]);
        }
    }
    __syncthreads();

    int gpix0 = (b * H + h) * W + w0;
    for (int i = tid; i < 64 * NPT; i += 256) {
        int pix = i & 63;
        int n = i >> 6;
        float ox = sacc[n * 64 + pix]        + bp[n];
        float oy = sacc[(9 + n) * 64 + pix]  + bp[9 + n];
        float mr = sacc[(18 + n) * 64 + pix] + bm[n];
        float m = 1.f / (1.f + expf(-mr));
        float px = ox + (float)(h + 1) + (float)(n / 3 - 1);
        float py = oy + (float)(w0 + pix + 1) + (float)(n % 3 - 1);
        float fx = floorf(px), fy = floorf(py);
        float qltx = fminf(fmaxf(fx,       0.f), 129.f);
        float qlty = fminf(fmaxf(fy,       0.f), 129.f);
        float qrbx = fminf(fmaxf(fx + 1.f, 0.f), 129.f);
        float qrby = fminf(fmaxf(fy + 1.f, 0.f), 129.f);
        float pxc = fminf(fmaxf(px, 0.f), 129.f);
        float pyc = fminf(fmaxf(py, 0.f), 129.f);
        float ax = 1.f + (qltx - pxc);
        float bx = 1.f - (qrbx - pxc);
        float ay = 1.f + (qlty - pyc);
        float by = 1.f - (qrby - pyc);
        int ilt_x = (int)qltx, ilt_y = (int)qlty;
        int irb_x = (int)qrbx, irb_y = (int)qrby;
        g_gates2[n * BHW + gpix0 + pix] = make_float4(ax * ay * m, bx * by * m, ax * by * m, bx * ay * m);
        g_offs2 [n * BHW + gpix0 + pix] = make_int4(ilt_x * WP + ilt_y, irb_x * WP + irb_y,
                                                    ilt_x * WP + irb_y, irb_x * WP + ilt_y);
    }
}

// ---------------------------------------------------------------------------
// Kernel 4: fused gather + bf16-split GEMM on warp-level mma (HMMA).
// CTA = 128 co x 128 pixels (one full image row), 256 thr, 2 CTAs/SM (73.7 KB).
// K = 1152 as 18 chunks of 64 (tap x ci-half). Warp layout 2M x 4N; B via ldmx4.
#define SMW_HI 0
#define SMW_LO 18432
#define SMU_HI 36864
#define SMU_LO 55296
#define SM_TOTAL 73728
__global__ __launch_bounds__(256, 2) void mma_main_kernel(float* __restrict__ out) {
    extern __shared__ __align__(128) char smem[];
    uint32_t sb = smem_u32(smem);
    int tid = threadIdx.x;
    int wid = tid >> 5, lane = tid & 31;

    int idx = blockIdx.x;              // 0..255 = b*H + h
    int b = idx >> 7, h = idx & 127;
    int gbase = idx * 128;             // pixel base (full row)

    const float4* xb4 = reinterpret_cast<const float4*>(g_xp) + (size_t)b * HP * WP * 32;

    int wm = (wid & 1) * 64;           // co half
    int wn = (wid >> 1) * 32;          // pixel quarter (32 pix)

    int asel = lane >> 3;
    int aRow = ((asel & 1) << 3) + (lane & 7);
    int aK = (asel >> 1) << 3;
    uint32_t aBase = (uint32_t)((wm + aRow) * 144 + aK * 2);
    // B ldmx4 lane mapping: covers 2 nt (16 pixels) per load
    uint32_t bBase = (uint32_t)((wn + ((lane >> 4) << 3) + (lane & 7)) * 144 +
                                (((lane >> 3) & 1) << 4));

    // gather mapping: warp owns 16 pixels; half-warp per pixel (16 lanes = 64 ci)
    int gp = wid * 16 + (lane >> 4);   // base pixel (+2*pp)
    int lq = lane & 15;                // ci quad within the 64-ci half

    float acc[4][4][4];
#pragma unroll
    for (int mt = 0; mt < 4; ++mt)
#pragma unroll
        for (int nt = 0; nt < 4; ++nt)
#pragma unroll
            for (int j = 0; j < 4; ++j) acc[mt][nt][j] = 0.f;

    for (int chunk = 0; chunk < 18; ++chunk) {
        int tap = chunk >> 1, half = chunk & 1;
        __syncthreads();   // U + W free (prev chunk's MMAs done)

        // stage W tile [128co][64k] hi+lo via cp.async (rows padded to 144B)
        {
            const float4* ah = reinterpret_cast<const float4*>(g_wA_hi) + chunk * 1024;
            const float4* al = reinterpret_cast<const float4*>(g_wA_lo) + chunk * 1024;
#pragma unroll
            for (int i = 0; i < 4; ++i) {
                int e = tid + i * 256;
                uint32_t off = (uint32_t)((e >> 3) * 144 + (e & 7) * 16);
                cp16(sb + SMW_HI + off, ah + e);
                cp16(sb + SMW_LO + off, al + e);
            }
            cp_commit();
        }

        // gather: 8 pixel-pairs per warp; 16 lanes cover one corner's 64-ci row
        const float4* xh = xb4 + half * 16;
#pragma unroll
        for (int pp = 0; pp < 8; ++pp) {
            int pix = gp + pp * 2;
            float4 g = g_gates2[tap * BHW + gbase + pix];
            int4  o = g_offs2 [tap * BHW + gbase + pix];
            float4 v0 = xh[(size_t)o.x * 32 + lq];
            float4 v1 = xh[(size_t)o.y * 32 + lq];
            float4 v2 = xh[(size_t)o.z * 32 + lq];
            float4 v3 = xh[(size_t)o.w * 32 + lq];
            float4 v;
            v.x = fmaf(g.w, v3.x, fmaf(g.z, v2.x, fmaf(g.y, v1.x, g.x * v0.x)));
            v.y = fmaf(g.w, v3.y, fmaf(g.z, v2.y, fmaf(g.y, v1.y, g.x * v0.y)));
            v.z = fmaf(g.w, v3.z, fmaf(g.z, v2.z, fmaf(g.y, v1.z, g.x * v0.z)));
            v.w = fmaf(g.w, v3.w, fmaf(g.z, v2.w, fmaf(g.y, v1.w, g.x * v0.w)));

            uint16_t hx, lx, hy, ly, hz, lz, hw_, lw_;
            bf16_split(v.x, hx, lx);
            bf16_split(v.y, hy, ly);
            bf16_split(v.z, hz, lz);
            bf16_split(v.w, hw_, lw_);

            uint32_t uoff = (uint32_t)(pix * 144 + lq * 8);
            *reinterpret_cast<uint2*>(smem + SMU_HI + uoff) = make_uint2(pack2(hx, hy), pack2(hz, hw_));
            *reinterpret_cast<uint2*>(smem + SMU_LO + uoff) = make_uint2(pack2(lx, ly), pack2(lz, lw_));
        }

        cp_wait<0>();
        __syncthreads();

        // HMMA: 4 k-steps of 16; B fragments cached (2 ldmx4 per hi/lo), A streamed
#pragma unroll
        for (int ks = 0; ks < 4; ++ks) {
            uint32_t BH[2][4], BL[2][4];
#pragma unroll
            for (int np = 0; np < 2; ++np) {
                uint32_t bo = bBase + (uint32_t)(np * 16 * 144 + ks * 32);
                ldmx4(BH[np], sb + SMU_HI + bo);
                ldmx4(BL[np], sb + SMU_LO + bo);
            }
#pragma unroll
            for (int mt = 0; mt < 4; ++mt) {
                uint32_t AH[4], AL[4];
                uint32_t ao = aBase + (uint32_t)(mt * 16 * 144 + ks * 32);
                ldmx4(AH, sb + SMW_HI + ao);
                ldmx4(AL, sb + SMW_LO + ao);
#pragma unroll
                for (int np = 0; np < 2; ++np) {
                    mma_bf16(acc[mt][np * 2],     AH, BH[np][0], BH[np][1]);
                    mma_bf16(acc[mt][np * 2],     AL, BH[np][0], BH[np][1]);
                    mma_bf16(acc[mt][np * 2],     AH, BL[np][0], BL[np][1]);
                    mma_bf16(acc[mt][np * 2 + 1], AH, BH[np][2], BH[np][3]);
                    mma_bf16(acc[mt][np * 2 + 1], AL, BH[np][2], BH[np][3]);
                    mma_bf16(acc[mt][np * 2 + 1], AH, BL[np][2], BL[np][3]);
                }
            }
        }
    }

    int g4 = lane >> 2, t4 = lane & 3;
#pragma unroll
    for (int mt = 0; mt < 4; ++mt) {
#pragma unroll
        for (int nt = 0; nt < 4; ++nt) {
            int co = wm + mt * 16 + g4;
            int px = wn + nt * 8 + t4 * 2;
            float* op = out + (((size_t)b * CO + co) * H + h) * W + px;
            *reinterpret_cast<float2*>(op) = make_float2(acc[mt][nt][0], acc[mt][nt][1]);
            float* op2 = out + (((size_t)b * CO + co + 8) * H + h) * W + px;
            *reinterpret_cast<float2*>(op2) = make_float2(acc[mt][nt][2], acc[mt][nt][3]);
        }
    }
}

// ---------------------------------------------------------------------------
extern "C" void kernel_launch(void* const* d_in, const int* in_sizes, int n_in,
                              void* d_out, int out_size) {
    const float* x      = (const float*)d_in[0];
    const float* w_p    = (const float*)d_in[1];
    const float* b_p    = (const float*)d_in[2];
    const float* w_m    = (const float*)d_in[3];
    const float* b_m    = (const float*)d_in[4];
    const float* w_conv = (const float*)d_in[5];
    float* out = (float*)d_out;

    cudaFuncSetAttribute(mma_main_kernel, cudaFuncAttributeMaxDynamicSharedMemorySize, SM_TOTAL);
    cudaFuncSetAttribute(conv_mma_kernel, cudaFuncAttributeMaxDynamicSharedMemorySize, SC_TOTAL);

    zero_border_kernel<<<(B * 516 * 32 + 255) / 256, 256>>>();
    prep_weights_kernel<<<720, 256>>>(w_p, w_m, w_conv);
    pad_transpose_kernel<<<dim3(W / 32, C / 32, B * H), dim3(32, 8)>>>(x);
    conv_mma_kernel<<<512, 256, SC_TOTAL>>>(b_p, b_m);
    mma_main_kernel<<<B * H, 256, SM_TOTAL>>>(out);
}